// round 16
// baseline (speedup 1.0000x reference)
#include <cuda_runtime.h>
#include <cuda_fp16.h>
#include <cstdint>
#include <math.h>

// ---------------- problem constants ----------------
#define IN_CH   512
#define OUT_CH  512
#define STYLE_DIM 512
#define B_SZ    8
#define NPIX    4096
#define CONV_SCALE (1.0f / 67.8822509939086f)   // 1/sqrt(512*9)
#define MOD_SCALE  (1.0f / 22.627416997969522f) // 1/sqrt(512)
#define EPSV 1e-8f

// ---------------- device scratch (no allocs allowed) ----------------
// Xs[b][row 0..65][x 0..63][i] : y-padded, sc-scaled input, fp16
__device__ __align__(16) __half g_Xs[(size_t)B_SZ * 66 * 64 * IN_CH];
// Wt[t][o][i] fp16 (K-major: i contiguous)
__device__ __align__(16) __half g_Wt[9 * OUT_CH * IN_CH];
__device__ float g_W2t[IN_CH * OUT_CH];   // [i][o]
__device__ float g_sc[B_SZ * IN_CH];      // CONV_SCALE * s[b,i]
__device__ float g_demod[B_SZ * OUT_CH];

// ---------------- PTX helpers (plain-target sm_80+ features only) ----
__device__ __forceinline__ uint32_t s2u(const void* p) {
    uint32_t a;
    asm("{ .reg .u64 t; cvta.to.shared.u64 t, %1; cvt.u32.u64 %0, t; }" : "=r"(a) : "l"(p));
    return a;
}
__device__ __forceinline__ void cp16(uint32_t d, const void* s) {
    asm volatile("cp.async.cg.shared.global [%0], [%1], 16;" :: "r"(d), "l"(s));
}
__device__ __forceinline__ void cp16z(uint32_t d, const void* s, uint32_t sz) {
    asm volatile("cp.async.cg.shared.global [%0], [%1], 16, %2;" :: "r"(d), "l"(s), "r"(sz));
}
__device__ __forceinline__ void ldsm4(uint32_t* r, uint32_t a) {
    asm volatile("ldmatrix.sync.aligned.m8n8.x4.shared.b16 {%0,%1,%2,%3}, [%4];"
        : "=r"(r[0]), "=r"(r[1]), "=r"(r[2]), "=r"(r[3]) : "r"(a));
}
// fp16 MMA: m16n8k16, fp32 accum
__device__ __forceinline__ void mma16(float* d, const uint32_t* a, uint32_t b0, uint32_t b1) {
    asm volatile("mma.sync.aligned.m16n8k16.row.col.f32.f16.f16.f32 "
        "{%0,%1,%2,%3},{%4,%5,%6,%7},{%8,%9},{%0,%1,%2,%3};"
        : "+f"(d[0]), "+f"(d[1]), "+f"(d[2]), "+f"(d[3])
        : "r"(a[0]), "r"(a[1]), "r"(a[2]), "r"(a[3]), "r"(b0), "r"(b1));
}

// ======================================================================
// Kernel 1: w5 = weight + relu(A @ relu(B @ B_inst)) -> g_Wt fp16 [t][o][i]
// and W2[i][o] = sum_t w5^2 (exact fp32).   grid 512 (per o), 256 thr
// ======================================================================
__global__ __launch_bounds__(256) void prep_w5_kernel(
    const float* __restrict__ weight, const float* __restrict__ llB,
    const float* __restrict__ llBinst, const float* __restrict__ llA)
{
    const int o = blockIdx.x;
    const int tid = threadIdx.x;
    __shared__ float Bo[4];
    __shared__ float Bm[4][9];

    if (tid < 4) Bo[tid] = llB[o * 4 + tid];
    __syncthreads();
    if (tid < 36) {
        int b_ = tid / 9, t = tid - b_ * 9;
        float acc = 0.f;
#pragma unroll
        for (int r = 0; r < 4; r++) acc += Bo[r] * llBinst[(b_ * 4 + r) * 9 + t];
        Bm[b_][t] = fmaxf(acc, 0.f);
    }
    __syncthreads();

    for (int i = tid; i < IN_CH; i += 256) {
        float A0 = llA[i * 4 + 0], A1 = llA[i * 4 + 1];
        float A2 = llA[i * 4 + 2], A3 = llA[i * 4 + 3];
        float w2sum = 0.f;
#pragma unroll
        for (int t = 0; t < 9; t++) {
            float add = fmaxf(A0 * Bm[0][t] + A1 * Bm[1][t] + A2 * Bm[2][t] + A3 * Bm[3][t], 0.f);
            float w = weight[(o * IN_CH + i) * 9 + t] + add;
            g_Wt[((size_t)t * OUT_CH + o) * IN_CH + i] = __float2half_rn(w);
            w2sum += w * w;
        }
        g_W2t[i * OUT_CH + o] = w2sum;
    }
}

// ======================================================================
// Kernel 2: sc[b,i] = CONV_SCALE * (MOD_SCALE * style @ w_fc.T + b_fc)
// ======================================================================
__global__ __launch_bounds__(512) void prep_s_kernel(
    const float* __restrict__ style, const float* __restrict__ modW,
    const float* __restrict__ modB, const float* __restrict__ fcA,
    const float* __restrict__ fcB, const float* __restrict__ fcBias)
{
    const int b  = blockIdx.x >> 3;
    const int i0 = (blockIdx.x & 7) << 6;
    const int tid = threadIdx.x;
    __shared__ float sty[STYLE_DIM];
    sty[tid] = style[b * STYLE_DIM + tid];
    __syncthreads();

    const int warp = tid >> 5, lane = tid & 31;
    for (int ii = warp; ii < 64; ii += 16) {
        const int i = i0 + ii;
        float4 fb = *(const float4*)&fcB[i * 4];
        float acc = 0.f;
        for (int j = lane; j < STYLE_DIM; j += 32) {
            float4 fa = *(const float4*)&fcA[j * 4];
            float wfc = modW[i * STYLE_DIM + j] +
                        (fb.x * fa.x + fb.y * fa.y + fb.z * fa.z + fb.w * fa.w);
            acc += sty[j] * wfc;
        }
#pragma unroll
        for (int off = 16; off; off >>= 1) acc += __shfl_xor_sync(0xFFFFFFFFu, acc, off);
        if (lane == 0) {
            float s = acc * MOD_SCALE + modB[i] + fcBias[i];
            g_sc[b * IN_CH + i] = s * CONV_SCALE;
        }
    }
}

// ======================================================================
// Kernel 3: demod[b,o] = rsqrt(sum_i sc^2 * W2[i][o] + eps)  (exact fp32)
// ======================================================================
__global__ __launch_bounds__(256) void prep_demod_kernel()
{
    const int id = blockIdx.x * 256 + threadIdx.x;
    const int b = id >> 9, o = id & 511;
    const float* scp = &g_sc[b * IN_CH];
    float acc = 0.f;
#pragma unroll 8
    for (int i = 0; i < IN_CH; i++) {
        float sv = scp[i];
        acc = fmaf(sv * sv, g_W2t[i * OUT_CH + o], acc);
    }
    g_demod[b * OUT_CH + o] = rsqrtf(acc + EPSV);
}

// ======================================================================
// Kernel 4: build Xs[b][row][x][i] = fp16( in[b][i][row-1][x] * sc[b,i] )
// rows 0 and 65 are zero padding. grid 528 = (b, row), 256 threads.
// ======================================================================
__global__ __launch_bounds__(256) void prep_xs_kernel(const float* __restrict__ input)
{
    const int b   = blockIdx.x / 66;
    const int row = blockIdx.x - b * 66;
    const int y   = row - 1;
    const bool valid = (unsigned)y < 64u;
    const int tid = threadIdx.x;

    __shared__ float tile[32][65];
    __shared__ float ssc[32];

    for (int i0 = 0; i0 < IN_CH; i0 += 32) {
        __syncthreads();
        if (tid < 32) ssc[tid] = g_sc[b * IN_CH + i0 + tid];
        if (valid) {
#pragma unroll
            for (int p = 0; p < 8; p++) {
                int idx = tid + p * 256;
                int ii = idx >> 6, x = idx & 63;
                tile[ii][x] = input[((size_t)b * IN_CH + i0 + ii) * NPIX + y * 64 + x];
            }
        }
        __syncthreads();
        size_t obase = (((size_t)b * 66 + row) * 64) * IN_CH;
#pragma unroll
        for (int p = 0; p < 4; p++) {
            int idx = tid + p * 256;      // 0..1023
            int x  = idx >> 4;            // 0..63
            int ip = (idx & 15) * 2;      // even i_local
            float s0 = 0.f, s1 = 0.f;
            if (valid) {
                s0 = tile[ip][x]     * ssc[ip];
                s1 = tile[ip + 1][x] * ssc[ip + 1];
            }
            *(__half2*)&g_Xs[obase + (size_t)x * IN_CH + i0 + ip] =
                __floats2half2_rn(s0, s1);
        }
    }
}

// ======================================================================
// Kernel 5: fp16 mma.sync implicit-GEMM conv with input-window reuse.
// CTA: M=256 px (4 y-rows: y = 4T..4T+3) x N=128 o. 512 threads,
// 16 warps (4 m-warps x 4 n-warps), warp tile 64x32.
// Outer loop: 8 i-chunks (K=64). Per chunk, ALL 9 taps read one shared
// 6-row x 66-col halo window (cells of 64 halves = 128B, swizzled by
// cell&7). B (per tap, 128o x 64i) streams via 3-stage cp.async pipeline,
// ONE __syncthreads per (chunk,tap).
// smem: 2 windows (2x50688) + 3 B stages (3x16384) = 150528 B -> 1 CTA/SM.
// grid (16 Mtiles, 4 Ntiles, 8 b) = 512 CTAs.
// ======================================================================
#define WIN_CELLS 396              // 6*66
#define WIN_BYTES (WIN_CELLS * 128)
#define BSTAGE_BYTES 16384
#define BBASE_OFF (2 * WIN_BYTES)  // 101376
#define DSMEM_BYTES (BBASE_OFF + 3 * BSTAGE_BYTES)  // 150528

__global__ __launch_bounds__(512, 1) void conv_tc_kernel(float* __restrict__ out)
{
    extern __shared__ __align__(16) char dyn[];
    __shared__ float sDm[128];

    const int T  = blockIdx.x;            // output rows 4T..4T+3
    const int o0 = blockIdx.y << 7;       // N tile base (128 o)
    const int b  = blockIdx.z;
    const int tid  = threadIdx.x;
    const int lane = tid & 31;
    const int wid  = tid >> 5;
    const int wm = wid >> 2;              // 0..3 (m warp: y-row 4T+wm)
    const int wn = wid & 3;               // 0..3 (n warp: 32 o)
    const uint32_t sbase = s2u(dyn);

    if (tid < 128) sDm[tid] = g_demod[b * OUT_CH + o0 + tid];

    // ---- B load constants: 1024 segs of 16B, 2 per thread ----
    const int gB0 = tid & 7, rB0 = tid >> 3;            // seg of (row rB0)
    const uint32_t dB0 = (uint32_t)(rB0 * 128) + (((uint32_t)gB0 << 4) ^ ((uint32_t)(rB0 & 7) << 4));
    const int gB1 = gB0, rB1 = rB0 + 64;
    const uint32_t dB1 = (uint32_t)(rB1 * 128) + (((uint32_t)gB1 << 4) ^ ((uint32_t)(rB1 & 7) << 4));

    // ---- compute-side constants ----
    const int rF  = lane & 15;            // fragment row (m for A, n for B)
    const int gh  = lane >> 4;            // k-half (16B)
    const uint32_t maskF = (uint32_t)((rF & 7) << 4);
    const uint32_t offB0 = (uint32_t)((wn * 32 + rF) * 128);
    // A cell bases: cell = cbm[mt] + kh*66 + kw ; cell = (wm+kh)*66 + x + kw
    int cbm[4];
#pragma unroll
    for (int mt = 0; mt < 4; mt++) cbm[mt] = wm * 66 + mt * 16 + rF;

    float acc[4][4][4];
#pragma unroll
    for (int mt = 0; mt < 4; mt++)
#pragma unroll
        for (int nt = 0; nt < 4; nt++)
#pragma unroll
            for (int q = 0; q < 4; q++) acc[mt][nt][q] = 0.f;

    const __half* Xb = g_Xs + ((size_t)b * 66) * 64 * IN_CH;

    // window loader: i-chunk ic -> buffer (ic&1). 3168 segs, <=7 per thread.
    auto load_win = [&](int ic) {
        const uint32_t wdst = sbase + (uint32_t)(ic & 1) * WIN_BYTES;
        const __half* src0 = Xb + (size_t)ic * 64;
#pragma unroll
        for (int l = 0; l < 7; l++) {
            int s = tid + 512 * l;
            if (s < WIN_CELLS * 8) {
                int cell = s >> 3, g = s & 7;
                int wr = cell / 66, wc = cell - wr * 66;
                int xs = wc - 1;
                uint32_t ok = ((unsigned)xs < 64u) ? 16u : 0u;
                int xc = ok ? xs : 0;
                const __half* src = src0 + ((size_t)(4 * T + wr) * 64 + xc) * IN_CH + g * 8;
                uint32_t dst = wdst + (uint32_t)(cell * 128) + (((uint32_t)g << 4) ^ ((uint32_t)(cell & 7) << 4));
                cp16z(dst, src, ok);
            }
        }
    };
    // B loader: chunk q = ic*9 + t -> stage q%3
    auto load_B = [&](int q) {
        const int ic = q / 9, t = q - 9 * ic;
        const uint32_t bdst = sbase + BBASE_OFF + (uint32_t)(q % 3) * BSTAGE_BYTES;
        const __half* wsrc = g_Wt + ((size_t)t * OUT_CH + o0) * IN_CH + ic * 64;
        cp16(bdst + dB0, wsrc + (size_t)rB0 * IN_CH + gB0 * 8);
        cp16(bdst + dB1, wsrc + (size_t)rB1 * IN_CH + gB1 * 8);
    };

    // ---- pipeline preamble ----
    load_win(0); load_B(0);
    asm volatile("cp.async.commit_group;" ::: "memory");
    load_B(1);
    asm volatile("cp.async.commit_group;" ::: "memory");

#pragma unroll 1
    for (int q = 0; q < 72; q++) {
        asm volatile("cp.async.wait_group 1;" ::: "memory");
        __syncthreads();
        // issue loads for q+2 (B always; window when q+2 starts a new i-chunk)
        if (q + 2 < 72) {
            load_B(q + 2);
            if (((q + 2) % 9) == 0) load_win((q + 2) / 9);
        }
        asm volatile("cp.async.commit_group;" ::: "memory");

        // ---- compute chunk q: tap t of i-chunk ic ----
        const int ic = q / 9, t = q - 9 * ic;
        const int kh = t / 3, kw = t - kh * 3;
        const int toff = kh * 66 + kw;
        const uint32_t aW = sbase + (uint32_t)(ic & 1) * WIN_BYTES;
        const uint32_t aB = sbase + BBASE_OFF + (uint32_t)(q % 3) * BSTAGE_BYTES;

#pragma unroll
        for (int ks = 0; ks < 4; ks++) {          // 4 k16 groups in K=64
            const uint32_t kseg = (uint32_t)((ks * 2 + gh) << 4);
            uint32_t af[4][4];
#pragma unroll
            for (int mt = 0; mt < 4; mt++) {
                const int cell = cbm[mt] + toff;
                const uint32_t aaddr = aW + (uint32_t)(cell * 128) + (kseg ^ ((uint32_t)(cell & 7) << 4));
                ldsm4(af[mt], aaddr);
            }
            const uint32_t kcol = ((uint32_t)(ks * 32 + gh * 16)) ^ maskF;
            uint32_t bf[2][4];
#pragma unroll
            for (int np = 0; np < 2; np++)
                ldsm4(bf[np], aB + offB0 + np * 2048 + kcol);
            // bf[np]: {n0-7 klo, n8-15 klo, n0-7 khi, n8-15 khi}
#pragma unroll
            for (int mt = 0; mt < 4; mt++) {
#pragma unroll
                for (int nt = 0; nt < 4; nt++) {
                    const int np = nt >> 1, h = nt & 1;
                    mma16(acc[mt][nt], af[mt], bf[np][h], bf[np][h + 2]);
                }
            }
        }
    }

    // ---- epilogue: y = 4T + wm; x = mt*16 + lane/4 (+8); n = wn*32+nt*8+2*(lane&3) (+1)
    const int y  = 4 * T + wm;
    const int xr = lane >> 2;
#pragma unroll
    for (int mt = 0; mt < 4; mt++) {
        const int x0 = mt * 16 + xr;
#pragma unroll
        for (int nt = 0; nt < 4; nt++) {
            const int n0 = wn * 32 + nt * 8 + 2 * (lane & 3);
            const float dm0 = sDm[n0], dm1 = sDm[n0 + 1];
            float* b0p = out + ((size_t)(b * OUT_CH + o0 + n0)) * NPIX + y * 64;
            float* b1p = b0p + NPIX;
            b0p[x0]     = acc[mt][nt][0] * dm0;
            b1p[x0]     = acc[mt][nt][1] * dm1;
            b0p[x0 + 8] = acc[mt][nt][2] * dm0;
            b1p[x0 + 8] = acc[mt][nt][3] * dm1;
        }
    }
}

// ======================================================================
extern "C" void kernel_launch(void* const* d_in, const int* in_sizes, int n_in,
                              void* d_out, int out_size)
{
    const float* input   = (const float*)d_in[0];
    const float* style   = (const float*)d_in[1];
    const float* weight  = (const float*)d_in[2];
    const float* llB     = (const float*)d_in[3];
    const float* llBinst = (const float*)d_in[4];
    const float* llA     = (const float*)d_in[5];
    const float* modW    = (const float*)d_in[6];
    const float* modB    = (const float*)d_in[7];
    const float* fcA     = (const float*)d_in[8];
    const float* fcB     = (const float*)d_in[9];
    const float* fcBias  = (const float*)d_in[10];
    float* out = (float*)d_out;

    cudaFuncSetAttribute(conv_tc_kernel,
                         cudaFuncAttributeMaxDynamicSharedMemorySize, DSMEM_BYTES);

    prep_w5_kernel<<<512, 256>>>(weight, llB, llBinst, llA);
    prep_s_kernel<<<64, 512>>>(style, modW, modB, fcA, fcB, fcBias);
    prep_demod_kernel<<<16, 256>>>();
    prep_xs_kernel<<<528, 256>>>(input);
    conv_tc_kernel<<<dim3(16, 4, 8), 512, DSMEM_BYTES>>>(out);
}

// round 17
// speedup vs baseline: 1.0877x; 1.0877x over previous
#include <cuda_runtime.h>
#include <cuda_fp16.h>
#include <cstdint>
#include <math.h>

// ---------------- problem constants ----------------
#define IN_CH   512
#define OUT_CH  512
#define STYLE_DIM 512
#define B_SZ    8
#define NPIX    4096
#define CONV_SCALE (1.0f / 67.8822509939086f)   // 1/sqrt(512*9)
#define MOD_SCALE  (1.0f / 22.627416997969522f) // 1/sqrt(512)
#define EPSV 1e-8f

// ---------------- device scratch (no allocs allowed) ----------------
// Xs[b][row 0..65][x 0..63][i] : y-padded, sc-scaled input, fp16
__device__ __align__(16) __half g_Xs[(size_t)B_SZ * 66 * 64 * IN_CH];
// Wt[t][o][i] fp16 (K-major: i contiguous)
__device__ __align__(16) __half g_Wt[9 * OUT_CH * IN_CH];
__device__ float g_W2t[IN_CH * OUT_CH];   // [i][o]
__device__ float g_sc[B_SZ * IN_CH];      // CONV_SCALE * s[b,i]
__device__ float g_demod[B_SZ * OUT_CH];

// ---------------- PTX helpers (plain-target sm_80+ features only) ----
__device__ __forceinline__ uint32_t s2u(const void* p) {
    uint32_t a;
    asm("{ .reg .u64 t; cvta.to.shared.u64 t, %1; cvt.u32.u64 %0, t; }" : "=r"(a) : "l"(p));
    return a;
}
__device__ __forceinline__ void cp16(uint32_t d, const void* s) {
    asm volatile("cp.async.cg.shared.global [%0], [%1], 16;" :: "r"(d), "l"(s));
}
__device__ __forceinline__ void cp16z(uint32_t d, const void* s, uint32_t sz) {
    asm volatile("cp.async.cg.shared.global [%0], [%1], 16, %2;" :: "r"(d), "l"(s), "r"(sz));
}
__device__ __forceinline__ void ldsm4(uint32_t* r, uint32_t a) {
    asm volatile("ldmatrix.sync.aligned.m8n8.x4.shared.b16 {%0,%1,%2,%3}, [%4];"
        : "=r"(r[0]), "=r"(r[1]), "=r"(r[2]), "=r"(r[3]) : "r"(a));
}
// fp16 MMA: m16n8k16, fp32 accum
__device__ __forceinline__ void mma16(float* d, const uint32_t* a, uint32_t b0, uint32_t b1) {
    asm volatile("mma.sync.aligned.m16n8k16.row.col.f32.f16.f16.f32 "
        "{%0,%1,%2,%3},{%4,%5,%6,%7},{%8,%9},{%0,%1,%2,%3};"
        : "+f"(d[0]), "+f"(d[1]), "+f"(d[2]), "+f"(d[3])
        : "r"(a[0]), "r"(a[1]), "r"(a[2]), "r"(a[3]), "r"(b0), "r"(b1));
}

// ======================================================================
// Kernel 1: w5 = weight + relu(A @ relu(B @ B_inst)) -> g_Wt fp16 [t][o][i]
// and W2[i][o] = sum_t w5^2 (exact fp32).   grid 512 (per o), 256 thr
// ======================================================================
__global__ __launch_bounds__(256) void prep_w5_kernel(
    const float* __restrict__ weight, const float* __restrict__ llB,
    const float* __restrict__ llBinst, const float* __restrict__ llA)
{
    const int o = blockIdx.x;
    const int tid = threadIdx.x;
    __shared__ float Bo[4];
    __shared__ float Bm[4][9];

    if (tid < 4) Bo[tid] = llB[o * 4 + tid];
    __syncthreads();
    if (tid < 36) {
        int b_ = tid / 9, t = tid - b_ * 9;
        float acc = 0.f;
#pragma unroll
        for (int r = 0; r < 4; r++) acc += Bo[r] * llBinst[(b_ * 4 + r) * 9 + t];
        Bm[b_][t] = fmaxf(acc, 0.f);
    }
    __syncthreads();

    for (int i = tid; i < IN_CH; i += 256) {
        float A0 = llA[i * 4 + 0], A1 = llA[i * 4 + 1];
        float A2 = llA[i * 4 + 2], A3 = llA[i * 4 + 3];
        float w2sum = 0.f;
#pragma unroll
        for (int t = 0; t < 9; t++) {
            float add = fmaxf(A0 * Bm[0][t] + A1 * Bm[1][t] + A2 * Bm[2][t] + A3 * Bm[3][t], 0.f);
            float w = weight[(o * IN_CH + i) * 9 + t] + add;
            g_Wt[((size_t)t * OUT_CH + o) * IN_CH + i] = __float2half_rn(w);
            w2sum += w * w;
        }
        g_W2t[i * OUT_CH + o] = w2sum;
    }
}

// ======================================================================
// Kernel 2: sc[b,i] = CONV_SCALE * (MOD_SCALE * style @ w_fc.T + b_fc)
// ======================================================================
__global__ __launch_bounds__(512) void prep_s_kernel(
    const float* __restrict__ style, const float* __restrict__ modW,
    const float* __restrict__ modB, const float* __restrict__ fcA,
    const float* __restrict__ fcB, const float* __restrict__ fcBias)
{
    const int b  = blockIdx.x >> 3;
    const int i0 = (blockIdx.x & 7) << 6;
    const int tid = threadIdx.x;
    __shared__ float sty[STYLE_DIM];
    sty[tid] = style[b * STYLE_DIM + tid];
    __syncthreads();

    const int warp = tid >> 5, lane = tid & 31;
    for (int ii = warp; ii < 64; ii += 16) {
        const int i = i0 + ii;
        float4 fb = *(const float4*)&fcB[i * 4];
        float acc = 0.f;
        for (int j = lane; j < STYLE_DIM; j += 32) {
            float4 fa = *(const float4*)&fcA[j * 4];
            float wfc = modW[i * STYLE_DIM + j] +
                        (fb.x * fa.x + fb.y * fa.y + fb.z * fa.z + fb.w * fa.w);
            acc += sty[j] * wfc;
        }
#pragma unroll
        for (int off = 16; off; off >>= 1) acc += __shfl_xor_sync(0xFFFFFFFFu, acc, off);
        if (lane == 0) {
            float s = acc * MOD_SCALE + modB[i] + fcBias[i];
            g_sc[b * IN_CH + i] = s * CONV_SCALE;
        }
    }
}

// ======================================================================
// Kernel 3: demod[b,o] = rsqrt(sum_i sc^2 * W2[i][o] + eps)  (exact fp32)
// ======================================================================
__global__ __launch_bounds__(256) void prep_demod_kernel()
{
    const int id = blockIdx.x * 256 + threadIdx.x;
    const int b = id >> 9, o = id & 511;
    const float* scp = &g_sc[b * IN_CH];
    float acc = 0.f;
#pragma unroll 8
    for (int i = 0; i < IN_CH; i++) {
        float sv = scp[i];
        acc = fmaf(sv * sv, g_W2t[i * OUT_CH + o], acc);
    }
    g_demod[b * OUT_CH + o] = rsqrtf(acc + EPSV);
}

// ======================================================================
// Kernel 4: build Xs[b][row][x][i] = fp16( in[b][i][row-1][x] * sc[b,i] )
// rows 0 and 65 are zero padding. grid 528 = (b, row), 256 threads.
// ======================================================================
__global__ __launch_bounds__(256) void prep_xs_kernel(const float* __restrict__ input)
{
    const int b   = blockIdx.x / 66;
    const int row = blockIdx.x - b * 66;
    const int y   = row - 1;
    const bool valid = (unsigned)y < 64u;
    const int tid = threadIdx.x;

    __shared__ float tile[32][65];
    __shared__ float ssc[32];

    for (int i0 = 0; i0 < IN_CH; i0 += 32) {
        __syncthreads();
        if (tid < 32) ssc[tid] = g_sc[b * IN_CH + i0 + tid];
        if (valid) {
#pragma unroll
            for (int p = 0; p < 8; p++) {
                int idx = tid + p * 256;
                int ii = idx >> 6, x = idx & 63;
                tile[ii][x] = input[((size_t)b * IN_CH + i0 + ii) * NPIX + y * 64 + x];
            }
        }
        __syncthreads();
        size_t obase = (((size_t)b * 66 + row) * 64) * IN_CH;
#pragma unroll
        for (int p = 0; p < 4; p++) {
            int idx = tid + p * 256;      // 0..1023
            int x  = idx >> 4;            // 0..63
            int ip = (idx & 15) * 2;      // even i_local
            float s0 = 0.f, s1 = 0.f;
            if (valid) {
                s0 = tile[ip][x]     * ssc[ip];
                s1 = tile[ip + 1][x] * ssc[ip + 1];
            }
            *(__half2*)&g_Xs[obase + (size_t)x * IN_CH + i0 + ip] =
                __floats2half2_rn(s0, s1);
        }
    }
}

// ======================================================================
// Kernel 5: fp16 mma.sync implicit-GEMM conv (R15 shape, 3-stage pipe).
// CTA: M=128 px (2 y-rows) x N=128 o. 8 warps (2 m x 4 n), warp tile 64x32.
// acc[4][4][4] = 64 regs/thread -> 2 CTAs/SM (16 warps).
// K loop: 9 taps x 8 chunks of K=64 halves (row = 128B, SW128 swizzle),
// cp.async TRIPLE-buffered (3 x 32KB), ONE __syncthreads per iteration:
//   compute stage it%3 while chunks it+1, it+2 stream into other stages.
// grid (32 Mtiles, 4 Ntiles, 8 b) = 1024 CTAs, 256 threads, 96KB dyn smem.
// ======================================================================
#define STAGE_BYTES 32768   // A 16384 + B 16384
#define DSMEM_BYTES (3 * STAGE_BYTES)

__global__ __launch_bounds__(256, 2) void conv_tc_kernel(float* __restrict__ out)
{
    extern __shared__ __align__(16) char dyn[];
    __shared__ float sDm[128];

    const int T  = blockIdx.x;            // M tile: output rows 2T..2T+1
    const int o0 = blockIdx.y << 7;       // N tile base (128 o)
    const int b  = blockIdx.z;
    const int tid  = threadIdx.x;
    const int lane = tid & 31;
    const int wid  = tid >> 5;
    const int wm = wid >> 2;              // 0..1  (m warp: 64 px = y-row wm)
    const int wn = wid & 3;               // 0..3  (n warp: 32 o)
    const uint32_t sbase = s2u(dyn);

    if (tid < 128) sDm[tid] = g_demod[b * OUT_CH + o0 + tid];

    // ---- load-side constants (16B segment = 8 halves; 128B row) ----
    const int g  = tid & 7;               // k-segment 0..7
    const int r0 = tid >> 3;              // base row 0..31; rows r0 + 32j
    const uint32_t dst0 = (uint32_t)(r0 * 128) + (((uint32_t)g * 16) ^ ((uint32_t)(r0 & 7) << 4));

    // ---- compute-side constants ----
    const int rF  = lane & 15;            // fragment row (m for A, n for B)
    const int gh  = lane >> 4;            // k-half (16B)
    const uint32_t maskF = (uint32_t)((rF & 7) << 4);
    const uint32_t offA0 = (uint32_t)((wm * 64 + rF) * 128);
    const uint32_t offB0 = (uint32_t)((wn * 32 + rF) * 128);

    float acc[4][4][4];
#pragma unroll
    for (int mt = 0; mt < 4; mt++)
#pragma unroll
        for (int nt = 0; nt < 4; nt++)
#pragma unroll
            for (int q = 0; q < 4; q++) acc[mt][nt][q] = 0.f;

    const __half* Xb = g_Xs + ((size_t)b * 66) * 64 * IN_CH;

    // chunk loader: it in 0..71 -> (tap = it>>3, i0 = (it&7)*64); stage 0..2
    auto load_chunk = [&](int it, int stage) {
        const int t  = it >> 3;
        const int i0 = (it & 7) << 6;
        const int kh = t / 3;
        const int kw = t - kh * 3;
        const int rowbase = 2 * T + kh;          // padded row of first pixel row
        const uint32_t sA = sbase + (uint32_t)stage * STAGE_BYTES;
        const uint32_t sB = sA + 16384;
        // A: 128 rows (pixels) x 64 halves
#pragma unroll
        for (int j = 0; j < 4; j++) {
            int px = r0 + 32 * j;
            int x  = px & 63;
            int xs = x + kw - 1;
            int yp = rowbase + (px >> 6);
            uint32_t ok = ((unsigned)xs < 64u) ? 16u : 0u;
            int xsc = ok ? xs : 0;
            const __half* src = Xb + ((size_t)yp * 64 + xsc) * IN_CH + i0 + g * 8;
            cp16z(sA + dst0 + j * 4096, src, ok);
        }
        // B: 128 rows (o) x 64 halves
        const __half* wsrc = g_Wt + ((size_t)t * OUT_CH + o0) * IN_CH + i0 + g * 8;
#pragma unroll
        for (int j = 0; j < 4; j++) {
            cp16(sB + dst0 + j * 4096, wsrc + (size_t)(r0 + 32 * j) * IN_CH);
        }
        asm volatile("cp.async.commit_group;" ::: "memory");
    };

    // ---- preamble: fill stages 0 and 1 ----
    load_chunk(0, 0);
    load_chunk(1, 1);

    int stage = 0;          // stage of chunk `it`
#pragma unroll 1
    for (int it = 0; it < 72; it++) {
        asm volatile("cp.async.wait_group 1;" ::: "memory");
        __syncthreads();     // data of stage `stage` visible; stage (it+2)%3 free
        if (it + 2 < 72) {
            int ns = stage + 2; if (ns >= 3) ns -= 3;
            load_chunk(it + 2, ns);
        } else {
            asm volatile("cp.async.commit_group;" ::: "memory"); // keep group count
        }

        const uint32_t aA = sbase + (uint32_t)stage * STAGE_BYTES;
        const uint32_t aB = aA + 16384;
#pragma unroll
        for (int ks = 0; ks < 4; ks++) {          // 4 k16 groups in K=64
            const uint32_t kcol = ((uint32_t)(ks * 32 + gh * 16)) ^ maskF;
            uint32_t af[4][4];
#pragma unroll
            for (int mt = 0; mt < 4; mt++)
                ldsm4(af[mt], aA + offA0 + mt * 2048 + kcol);
            uint32_t bf[2][4];
#pragma unroll
            for (int np = 0; np < 2; np++)
                ldsm4(bf[np], aB + offB0 + np * 2048 + kcol);
            // bf[np]: {n0-7 klo, n8-15 klo, n0-7 khi, n8-15 khi} for n-group np
#pragma unroll
            for (int mt = 0; mt < 4; mt++) {
#pragma unroll
                for (int nt = 0; nt < 4; nt++) {
                    const int np = nt >> 1, h = nt & 1;
                    mma16(acc[mt][nt], af[mt], bf[np][h], bf[np][h + 2]);
                }
            }
        }
        if (++stage == 3) stage = 0;
    }

    // ---- epilogue: y = 2T + wm; x = mt*16 + lane/4 (+8); n = wn*32+nt*8+2*(lane&3) (+1)
    const int y  = 2 * T + wm;
    const int xr = lane >> 2;
#pragma unroll
    for (int mt = 0; mt < 4; mt++) {
        const int x0 = mt * 16 + xr;
#pragma unroll
        for (int nt = 0; nt < 4; nt++) {
            const int n0 = wn * 32 + nt * 8 + 2 * (lane & 3);
            const float dm0 = sDm[n0], dm1 = sDm[n0 + 1];
            float* b0p = out + ((size_t)(b * OUT_CH + o0 + n0)) * NPIX + y * 64;
            float* b1p = b0p + NPIX;
            b0p[x0]     = acc[mt][nt][0] * dm0;
            b1p[x0]     = acc[mt][nt][1] * dm1;
            b0p[x0 + 8] = acc[mt][nt][2] * dm0;
            b1p[x0 + 8] = acc[mt][nt][3] * dm1;
        }
    }
}

// ======================================================================
extern "C" void kernel_launch(void* const* d_in, const int* in_sizes, int n_in,
                              void* d_out, int out_size)
{
    const float* input   = (const float*)d_in[0];
    const float* style   = (const float*)d_in[1];
    const float* weight  = (const float*)d_in[2];
    const float* llB     = (const float*)d_in[3];
    const float* llBinst = (const float*)d_in[4];
    const float* llA     = (const float*)d_in[5];
    const float* modW    = (const float*)d_in[6];
    const float* modB    = (const float*)d_in[7];
    const float* fcA     = (const float*)d_in[8];
    const float* fcB     = (const float*)d_in[9];
    const float* fcBias  = (const float*)d_in[10];
    float* out = (float*)d_out;

    cudaFuncSetAttribute(conv_tc_kernel,
                         cudaFuncAttributeMaxDynamicSharedMemorySize, DSMEM_BYTES);

    prep_w5_kernel<<<512, 256>>>(weight, llB, llBinst, llA);
    prep_s_kernel<<<64, 512>>>(style, modW, modB, fcA, fcB, fcBias);
    prep_demod_kernel<<<16, 256>>>();
    prep_xs_kernel<<<528, 256>>>(input);
    conv_tc_kernel<<<dim3(32, 4, 8), 256, DSMEM_BYTES>>>(out);
}